// round 1
// baseline (speedup 1.0000x reference)
#include <cuda_runtime.h>

#define N_NODES 50000
#define N_EDGES 800000
#define IN_CH   256
#define HC      128
#define N_TOT   384          // [xm_lower | xm_upper | skip]
#define EPSF    (1.0f + 1e-6f)
#define NEG_SLOPE 0.01f

// ---------------- scratch (__device__ globals: no allocs allowed) ------------
__device__ float g_Wcat[IN_CH * N_TOT];                 // 384 KB
__device__ float g_XM[(size_t)N_NODES * N_TOT];         // 76.8 MB
__device__ float g_asrc_l[N_NODES * 2];
__device__ float g_adst_l[N_NODES * 2];
__device__ float g_asrc_u[N_NODES * 2];
__device__ float g_adst_u[N_NODES * 2];
__device__ int   g_off_l[N_NODES + 1];
__device__ int   g_off_u[N_NODES + 1];

// ---------------- pack W_lower|W_upper|W_skip*EPS into one B matrix ----------
__global__ void pack_w_kernel(const float* __restrict__ Wl,
                              const float* __restrict__ Wu,
                              const float* __restrict__ Ws) {
    int i = blockIdx.x * blockDim.x + threadIdx.x;
    if (i < IN_CH * HC) {
        int k = i / HC, n = i % HC;
        g_Wcat[k * N_TOT + n]       = Wl[i];
        g_Wcat[k * N_TOT + 128 + n] = Wu[i];
        g_Wcat[k * N_TOT + 256 + n] = Ws[i] * EPSF;
    }
}

// ---------------- fp32 tiled GEMM: XM[M,384] = x[M,256] @ Wcat[256,384] ------
#define BM 128
#define BN 128
#define BK 16

__global__ __launch_bounds__(256, 2) void gemm_kernel(const float* __restrict__ X) {
    __shared__ float As[BK][BM + 4];   // +4 pad: avoid transpose-store conflicts
    __shared__ float Bs[BK][BN];

    const int t    = threadIdx.x;
    const int row0 = blockIdx.x * BM;
    const int col0 = blockIdx.y * BN;
    const int ty   = t >> 4;           // 0..15
    const int tx   = t & 15;           // 0..15

    float acc[8][8];
    #pragma unroll
    for (int i = 0; i < 8; i++)
        #pragma unroll
        for (int j = 0; j < 8; j++) acc[i][j] = 0.f;

    for (int k0 = 0; k0 < IN_CH; k0 += BK) {
        // load A tile (128 rows x 16 k), transpose into As[k][m]
        #pragma unroll
        for (int j = 0; j < 2; j++) {
            int f  = t + j * 256;          // 0..511 float4 slots
            int m  = f >> 2;               // row within tile
            int kk = (f & 3) * 4;          // k within tile
            float4 v = make_float4(0.f, 0.f, 0.f, 0.f);
            int gr = row0 + m;
            if (gr < N_NODES)
                v = *(const float4*)(X + (size_t)gr * IN_CH + k0 + kk);
            As[kk + 0][m] = v.x; As[kk + 1][m] = v.y;
            As[kk + 2][m] = v.z; As[kk + 3][m] = v.w;
        }
        // load B tile (16 k x 128 n)
        #pragma unroll
        for (int j = 0; j < 2; j++) {
            int f  = t + j * 256;
            int kk = f >> 5;
            int n4 = (f & 31) * 4;
            *(float4*)&Bs[kk][n4] =
                *(const float4*)(g_Wcat + (size_t)(k0 + kk) * N_TOT + col0 + n4);
        }
        __syncthreads();

        #pragma unroll
        for (int kk = 0; kk < BK; kk++) {
            float a[8], b[8];
            #pragma unroll
            for (int i = 0; i < 8; i++) a[i] = As[kk][ty * 8 + i];
            #pragma unroll
            for (int j = 0; j < 8; j++) b[j] = Bs[kk][tx * 8 + j];
            #pragma unroll
            for (int i = 0; i < 8; i++)
                #pragma unroll
                for (int j = 0; j < 8; j++)
                    acc[i][j] += a[i] * b[j];
        }
        __syncthreads();
    }

    #pragma unroll
    for (int i = 0; i < 8; i++) {
        int gr = row0 + ty * 8 + i;
        if (gr < N_NODES) {
            #pragma unroll
            for (int j = 0; j < 8; j += 4) {
                float4 v = make_float4(acc[i][j], acc[i][j + 1],
                                       acc[i][j + 2], acc[i][j + 3]);
                *(float4*)(g_XM + (size_t)gr * N_TOT + col0 + tx * 8 + j) = v;
            }
        }
    }
}

// ---------------- per-node attention alphas (warp per node) ------------------
__device__ __forceinline__ float lrelu(float v) {
    return v >= 0.f ? v : NEG_SLOPE * v;
}

__global__ __launch_bounds__(256) void alpha_kernel(
    const float* __restrict__ asl, const float* __restrict__ adl,
    const float* __restrict__ asu, const float* __restrict__ adu) {
    int wid  = (blockIdx.x * blockDim.x + threadIdx.x) >> 5;
    int lane = threadIdx.x & 31;
    if (wid >= N_NODES) return;

    const float* row = g_XM + (size_t)wid * N_TOT;
    float4 xl = *(const float4*)(row + lane * 4);          // lower xm row
    float4 xu = *(const float4*)(row + 128 + lane * 4);    // upper xm row
    float4 vsl = *(const float4*)(asl + lane * 4);
    float4 vdl = *(const float4*)(adl + lane * 4);
    float4 vsu = *(const float4*)(asu + lane * 4);
    float4 vdu = *(const float4*)(adu + lane * 4);

    float psl = xl.x * vsl.x + xl.y * vsl.y + xl.z * vsl.z + xl.w * vsl.w;
    float pdl = xl.x * vdl.x + xl.y * vdl.y + xl.z * vdl.z + xl.w * vdl.w;
    float psu = xu.x * vsu.x + xu.y * vsu.y + xu.z * vsu.z + xu.w * vsu.w;
    float pdu = xu.x * vdu.x + xu.y * vdu.y + xu.z * vdu.z + xu.w * vdu.w;

    // reduce within each 16-lane half (head 0: lanes 0-15, head 1: lanes 16-31)
    #pragma unroll
    for (int m = 8; m >= 1; m >>= 1) {
        psl += __shfl_xor_sync(0xFFFFFFFFu, psl, m);
        pdl += __shfl_xor_sync(0xFFFFFFFFu, pdl, m);
        psu += __shfl_xor_sync(0xFFFFFFFFu, psu, m);
        pdu += __shfl_xor_sync(0xFFFFFFFFu, pdu, m);
    }
    if (lane == 0 || lane == 16) {
        int h = lane >> 4;
        g_asrc_l[wid * 2 + h] = lrelu(psl);
        g_adst_l[wid * 2 + h] = lrelu(pdl);
        g_asrc_u[wid * 2 + h] = lrelu(psu);
        g_adst_u[wid * 2 + h] = lrelu(pdu);
    }
}

// ---------------- CSR offsets via binary search (tgt arrays are sorted) ------
__device__ __forceinline__ int lower_bound_dev(const int* __restrict__ a, int key) {
    int lo = 0, hi = N_EDGES;
    while (lo < hi) {
        int mid = (lo + hi) >> 1;
        if (a[mid] < key) lo = mid + 1; else hi = mid;
    }
    return lo;
}

__global__ void offsets_kernel(const int* __restrict__ tgt_l,
                               const int* __restrict__ tgt_u) {
    int t = blockIdx.x * blockDim.x + threadIdx.x;
    if (t > N_NODES) return;
    g_off_l[t] = lower_bound_dev(tgt_l, t);
    g_off_u[t] = lower_bound_dev(tgt_u, t);
}

// ---------------- fused aggregation: skip + lower + upper + relu -------------
// One warp owns node n: 4 channels per lane, lanes 0-15 = head 0, 16-31 = head 1.
// NOTE: softmax over heads is invariant to the per-edge `vals` (constant across
// heads), so vals never need to be read.
__global__ __launch_bounds__(256) void aggregate_kernel(
    const int* __restrict__ srcL, const int* __restrict__ srcU,
    float* __restrict__ out) {
    int wid  = (blockIdx.x * blockDim.x + threadIdx.x) >> 5;
    int lane = threadIdx.x & 31;
    if (wid >= N_NODES) return;

    const bool h0 = lane < 16;
    // init with skip term (EPS already folded into Wcat)
    float4 acc = *(const float4*)(g_XM + (size_t)wid * N_TOT + 256 + lane * 4);

    // ---- lower adjacency ----
    {
        float ad0 = g_adst_l[wid * 2], ad1 = g_adst_l[wid * 2 + 1];
        int e1 = g_off_l[wid + 1];
        for (int e = g_off_l[wid]; e < e1; e++) {
            int s = __ldg(srcL + e);
            float s0 = g_asrc_l[2 * s]     + ad0;
            float s1 = g_asrc_l[2 * s + 1] + ad1;
            float mx = fmaxf(s0, s1);
            float ea = __expf(s0 - mx), eb = __expf(s1 - mx);
            float w  = (h0 ? ea : eb) / (ea + eb);
            float4 xv = *(const float4*)(g_XM + (size_t)s * N_TOT + lane * 4);
            acc.x += xv.x * w; acc.y += xv.y * w;
            acc.z += xv.z * w; acc.w += xv.w * w;
        }
    }
    // ---- upper adjacency ----
    {
        float ad0 = g_adst_u[wid * 2], ad1 = g_adst_u[wid * 2 + 1];
        int e1 = g_off_u[wid + 1];
        for (int e = g_off_u[wid]; e < e1; e++) {
            int s = __ldg(srcU + e);
            float s0 = g_asrc_u[2 * s]     + ad0;
            float s1 = g_asrc_u[2 * s + 1] + ad1;
            float mx = fmaxf(s0, s1);
            float ea = __expf(s0 - mx), eb = __expf(s1 - mx);
            float w  = (h0 ? ea : eb) / (ea + eb);
            float4 xv = *(const float4*)(g_XM + (size_t)s * N_TOT + 128 + lane * 4);
            acc.x += xv.x * w; acc.y += xv.y * w;
            acc.z += xv.z * w; acc.w += xv.w * w;
        }
    }

    acc.x = fmaxf(acc.x, 0.f); acc.y = fmaxf(acc.y, 0.f);
    acc.z = fmaxf(acc.z, 0.f); acc.w = fmaxf(acc.w, 0.f);
    *(float4*)(out + (size_t)wid * HC + lane * 4) = acc;
}

// ---------------- launch ------------------------------------------------------
extern "C" void kernel_launch(void* const* d_in, const int* in_sizes, int n_in,
                              void* d_out, int out_size) {
    const float* x          = (const float*)d_in[0];
    const int*   lower_tgt  = (const int*)  d_in[1];
    const int*   lower_src  = (const int*)  d_in[2];
    // d_in[3] lower_vals: unused (cancels in head-axis softmax)
    const int*   upper_tgt  = (const int*)  d_in[4];
    const int*   upper_src  = (const int*)  d_in[5];
    // d_in[6] upper_vals: unused
    const float* W_lower    = (const float*)d_in[7];
    const float* a_src_l    = (const float*)d_in[8];
    const float* a_dst_l    = (const float*)d_in[9];
    const float* W_upper    = (const float*)d_in[10];
    const float* a_src_u    = (const float*)d_in[11];
    const float* a_dst_u    = (const float*)d_in[12];
    const float* W_skip     = (const float*)d_in[13];
    float* out = (float*)d_out;

    pack_w_kernel<<<(IN_CH * HC + 255) / 256, 256>>>(W_lower, W_upper, W_skip);

    dim3 gg((N_NODES + BM - 1) / BM, N_TOT / BN);
    gemm_kernel<<<gg, 256>>>(x);

    alpha_kernel<<<(N_NODES * 32 + 255) / 256, 256>>>(a_src_l, a_dst_l,
                                                      a_src_u, a_dst_u);
    offsets_kernel<<<(N_NODES + 1 + 255) / 256, 256>>>(lower_tgt, upper_tgt);
    aggregate_kernel<<<(N_NODES * 32 + 255) / 256, 256>>>(lower_src, upper_src, out);
}

// round 3
// speedup vs baseline: 1.7594x; 1.7594x over previous
#include <cuda_runtime.h>
#include <cstdint>

#define N_NODES 50000
#define N_EDGES 800000
#define IN_CH   256
#define HC      128
#define N_TOT   384          // [xm_lower | xm_upper | skip]
#define EPSF    (1.0f + 1e-6f)
#define NEG_SLOPE 0.01f

// ---------------- scratch (__device__ globals: no allocs allowed) ------------
__device__ float g_Wcat[IN_CH * N_TOT];                 // 384 KB (tf32-rounded)
__device__ float g_XM[(size_t)N_NODES * N_TOT];         // 76.8 MB
__device__ float g_asrc_l[N_NODES * 2];
__device__ float g_adst_l[N_NODES * 2];
__device__ float g_asrc_u[N_NODES * 2];
__device__ float g_adst_u[N_NODES * 2];
__device__ int   g_off_l[N_NODES + 1];
__device__ int   g_off_u[N_NODES + 1];

__device__ __forceinline__ uint32_t f2tf32(float v) {
    uint32_t u;
    asm("cvt.rna.tf32.f32 %0, %1;" : "=r"(u) : "f"(v));
    return u;
}

// ---------------- pack: W_lower|W_upper|W_skip*EPS -> g_Wcat (tf32) ----------
__global__ void pack_w_kernel(const float* __restrict__ Wl,
                              const float* __restrict__ Wu,
                              const float* __restrict__ Ws) {
    int i = blockIdx.x * blockDim.x + threadIdx.x;
    if (i >= IN_CH * HC) return;
    int k = i / HC, n = i % HC;
    g_Wcat[k * N_TOT + n]       = __uint_as_float(f2tf32(Wl[i]));
    g_Wcat[k * N_TOT + 128 + n] = __uint_as_float(f2tf32(Wu[i]));
    g_Wcat[k * N_TOT + 256 + n] = __uint_as_float(f2tf32(Ws[i] * EPSF));
}

// ---------------- tf32 mma.sync GEMM: XM[50000,384] = x @ Wcat ---------------
#define BM 128
#define BN 128
#define BK 32
#define AS_STR 36     // 144B rows: 16B-aligned, conflict-free A-frag loads
#define BS_STR 136    // 544B rows: 16B-aligned, conflict-free B-frag loads

__device__ __forceinline__ void mma_tf32(float* c, const uint32_t* a,
                                         uint32_t b0, uint32_t b1) {
    asm volatile(
        "mma.sync.aligned.m16n8k8.row.col.f32.tf32.tf32.f32 "
        "{%0,%1,%2,%3}, {%4,%5,%6,%7}, {%8,%9}, {%0,%1,%2,%3};"
        : "+f"(c[0]), "+f"(c[1]), "+f"(c[2]), "+f"(c[3])
        : "r"(a[0]), "r"(a[1]), "r"(a[2]), "r"(a[3]), "r"(b0), "r"(b1));
}

__global__ __launch_bounds__(256, 2) void gemm_kernel(const float* __restrict__ X) {
    __shared__ uint32_t As[BM * AS_STR];   // 18.0 KB
    __shared__ uint32_t Bs[BK * BS_STR];   // 17.0 KB

    const int t    = threadIdx.x;
    const int lane = t & 31;
    const int wid  = t >> 5;
    const int row0 = blockIdx.x * BM;
    const int col0 = blockIdx.y * BN;
    const int wm   = (wid & 3) * 32;       // warp M origin within tile
    const int wn   = (wid >> 2) * 64;      // warp N origin within tile
    const int g    = lane >> 2;            // 0..7
    const int c    = lane & 3;             // 0..3

    float acc[2][8][4];
    #pragma unroll
    for (int mf = 0; mf < 2; mf++)
        #pragma unroll
        for (int nf = 0; nf < 8; nf++)
            #pragma unroll
            for (int j = 0; j < 4; j++) acc[mf][nf][j] = 0.f;

    const uint32_t* Wc = (const uint32_t*)g_Wcat;

    for (int k0 = 0; k0 < IN_CH; k0 += BK) {
        // ---- A tile [128 m][32 k], cvt to tf32 ----
        #pragma unroll
        for (int i = 0; i < 4; i++) {
            int slot = t + i * 256;          // 0..1023 float4 slots
            int m    = slot >> 3;
            int k4   = (slot & 7) * 4;
            float4 v = make_float4(0.f, 0.f, 0.f, 0.f);
            int gr = row0 + m;
            if (gr < N_NODES)
                v = *(const float4*)(X + (size_t)gr * IN_CH + k0 + k4);
            *(uint4*)&As[m * AS_STR + k4] =
                make_uint4(f2tf32(v.x), f2tf32(v.y), f2tf32(v.z), f2tf32(v.w));
        }
        // ---- B tile [32 k][128 n] (already tf32) ----
        #pragma unroll
        for (int i = 0; i < 4; i++) {
            int slot = t + i * 256;
            int kk   = slot >> 5;
            int n4   = (slot & 31) * 4;
            *(uint4*)&Bs[kk * BS_STR + n4] =
                *(const uint4*)(Wc + (size_t)(k0 + kk) * N_TOT + col0 + n4);
        }
        __syncthreads();

        #pragma unroll
        for (int ks = 0; ks < 4; ks++) {
            const int kb = ks * 8;
            uint32_t a[2][4];
            #pragma unroll
            for (int mf = 0; mf < 2; mf++) {
                int m = wm + mf * 16;
                a[mf][0] = As[(m + g)     * AS_STR + kb + c];
                a[mf][1] = As[(m + g + 8) * AS_STR + kb + c];
                a[mf][2] = As[(m + g)     * AS_STR + kb + c + 4];
                a[mf][3] = As[(m + g + 8) * AS_STR + kb + c + 4];
            }
            #pragma unroll
            for (int nf = 0; nf < 8; nf++) {
                uint32_t b0 = Bs[(kb + c)     * BS_STR + wn + nf * 8 + g];
                uint32_t b1 = Bs[(kb + c + 4) * BS_STR + wn + nf * 8 + g];
                mma_tf32(acc[0][nf], a[0], b0, b1);
                mma_tf32(acc[1][nf], a[1], b0, b1);
            }
        }
        __syncthreads();
    }

    // ---- epilogue: float2 stores straight to g_XM ----
    #pragma unroll
    for (int mf = 0; mf < 2; mf++) {
        int r1 = row0 + wm + mf * 16 + g;
        int r2 = r1 + 8;
        #pragma unroll
        for (int nf = 0; nf < 8; nf++) {
            int cc = col0 + wn + nf * 8 + c * 2;
            if (r1 < N_NODES)
                *(float2*)(g_XM + (size_t)r1 * N_TOT + cc) =
                    make_float2(acc[mf][nf][0], acc[mf][nf][1]);
            if (r2 < N_NODES)
                *(float2*)(g_XM + (size_t)r2 * N_TOT + cc) =
                    make_float2(acc[mf][nf][2], acc[mf][nf][3]);
        }
    }
}

// ---------------- per-node attention alphas (warp per node) ------------------
__device__ __forceinline__ float lrelu(float v) {
    return v >= 0.f ? v : NEG_SLOPE * v;
}

__global__ __launch_bounds__(256) void alpha_kernel(
    const float* __restrict__ asl, const float* __restrict__ adl,
    const float* __restrict__ asu, const float* __restrict__ adu) {
    int wid  = (blockIdx.x * blockDim.x + threadIdx.x) >> 5;
    int lane = threadIdx.x & 31;
    if (wid >= N_NODES) return;

    const float* row = g_XM + (size_t)wid * N_TOT;
    float4 xl  = *(const float4*)(row + lane * 4);
    float4 xu  = *(const float4*)(row + 128 + lane * 4);
    float4 vsl = *(const float4*)(asl + lane * 4);
    float4 vdl = *(const float4*)(adl + lane * 4);
    float4 vsu = *(const float4*)(asu + lane * 4);
    float4 vdu = *(const float4*)(adu + lane * 4);

    float psl = xl.x * vsl.x + xl.y * vsl.y + xl.z * vsl.z + xl.w * vsl.w;
    float pdl = xl.x * vdl.x + xl.y * vdl.y + xl.z * vdl.z + xl.w * vdl.w;
    float psu = xu.x * vsu.x + xu.y * vsu.y + xu.z * vsu.z + xu.w * vsu.w;
    float pdu = xu.x * vdu.x + xu.y * vdu.y + xu.z * vdu.z + xu.w * vdu.w;

    #pragma unroll
    for (int m = 8; m >= 1; m >>= 1) {
        psl += __shfl_xor_sync(0xFFFFFFFFu, psl, m);
        pdl += __shfl_xor_sync(0xFFFFFFFFu, pdl, m);
        psu += __shfl_xor_sync(0xFFFFFFFFu, psu, m);
        pdu += __shfl_xor_sync(0xFFFFFFFFu, pdu, m);
    }
    if (lane == 0 || lane == 16) {
        int h = lane >> 4;
        g_asrc_l[wid * 2 + h] = lrelu(psl);
        g_adst_l[wid * 2 + h] = lrelu(pdl);
        g_asrc_u[wid * 2 + h] = lrelu(psu);
        g_adst_u[wid * 2 + h] = lrelu(pdu);
    }
}

// ---------------- CSR offsets via boundary scatter (tgt sorted) --------------
__global__ void offsets_kernel(const int* __restrict__ tl,
                               const int* __restrict__ tu) {
    int e = blockIdx.x * blockDim.x + threadIdx.x;
    if (e > N_EDGES) return;
    {
        int cur  = (e < N_EDGES) ? __ldg(tl + e) : N_NODES;
        int prev = (e > 0) ? __ldg(tl + e - 1) : -1;
        for (int v = prev + 1; v <= cur; v++) g_off_l[v] = e;
    }
    {
        int cur  = (e < N_EDGES) ? __ldg(tu + e) : N_NODES;
        int prev = (e > 0) ? __ldg(tu + e - 1) : -1;
        for (int v = prev + 1; v <= cur; v++) g_off_u[v] = e;
    }
}

// ---------------- fused aggregation: skip + lower + upper + relu -------------
// Warp per node; lanes 0-15 head 0, 16-31 head 1; 4 channels/lane.
// Per-edge `vals` cancel in the head-axis softmax -> never loaded.
__global__ __launch_bounds__(256) void aggregate_kernel(
    const int* __restrict__ srcL, const int* __restrict__ srcU,
    float* __restrict__ out) {
    int wid  = (blockIdx.x * blockDim.x + threadIdx.x) >> 5;
    int lane = threadIdx.x & 31;
    if (wid >= N_NODES) return;

    const bool h0 = lane < 16;
    float4 acc = *(const float4*)(g_XM + (size_t)wid * N_TOT + 256 + lane * 4);

    {
        float2 ad = *(const float2*)(g_adst_l + wid * 2);
        int e1 = g_off_l[wid + 1];
        for (int e = g_off_l[wid]; e < e1; e++) {
            int s = __ldg(srcL + e);
            float2 as = *(const float2*)(g_asrc_l + 2 * s);
            float s0 = as.x + ad.x, s1 = as.y + ad.y;
            float d  = h0 ? (s1 - s0) : (s0 - s1);
            float w  = 1.f / (1.f + __expf(d));
            float4 xv = *(const float4*)(g_XM + (size_t)s * N_TOT + lane * 4);
            acc.x += xv.x * w; acc.y += xv.y * w;
            acc.z += xv.z * w; acc.w += xv.w * w;
        }
    }
    {
        float2 ad = *(const float2*)(g_adst_u + wid * 2);
        int e1 = g_off_u[wid + 1];
        for (int e = g_off_u[wid]; e < e1; e++) {
            int s = __ldg(srcU + e);
            float2 as = *(const float2*)(g_asrc_u + 2 * s);
            float s0 = as.x + ad.x, s1 = as.y + ad.y;
            float d  = h0 ? (s1 - s0) : (s0 - s1);
            float w  = 1.f / (1.f + __expf(d));
            float4 xv = *(const float4*)(g_XM + (size_t)s * N_TOT + 128 + lane * 4);
            acc.x += xv.x * w; acc.y += xv.y * w;
            acc.z += xv.z * w; acc.w += xv.w * w;
        }
    }

    acc.x = fmaxf(acc.x, 0.f); acc.y = fmaxf(acc.y, 0.f);
    acc.z = fmaxf(acc.z, 0.f); acc.w = fmaxf(acc.w, 0.f);
    *(float4*)(out + (size_t)wid * HC + lane * 4) = acc;
}

// ---------------- launch ------------------------------------------------------
extern "C" void kernel_launch(void* const* d_in, const int* in_sizes, int n_in,
                              void* d_out, int out_size) {
    const float* x         = (const float*)d_in[0];
    const int*   lower_tgt = (const int*)  d_in[1];
    const int*   lower_src = (const int*)  d_in[2];
    const int*   upper_tgt = (const int*)  d_in[4];
    const int*   upper_src = (const int*)  d_in[5];
    const float* W_lower   = (const float*)d_in[7];
    const float* a_src_l   = (const float*)d_in[8];
    const float* a_dst_l   = (const float*)d_in[9];
    const float* W_upper   = (const float*)d_in[10];
    const float* a_src_u   = (const float*)d_in[11];
    const float* a_dst_u   = (const float*)d_in[12];
    const float* W_skip    = (const float*)d_in[13];
    float* out = (float*)d_out;

    pack_w_kernel<<<(IN_CH * HC + 255) / 256, 256>>>(W_lower, W_upper, W_skip);

    dim3 gg((N_NODES + BM - 1) / BM, N_TOT / BN);   // 391 x 3
    gemm_kernel<<<gg, 256>>>(x);

    alpha_kernel<<<(N_NODES * 32 + 255) / 256, 256>>>(a_src_l, a_dst_l,
                                                      a_src_u, a_dst_u);
    offsets_kernel<<<(N_EDGES + 1 + 255) / 256, 256>>>(lower_tgt, upper_tgt);
    aggregate_kernel<<<(N_NODES * 32 + 255) / 256, 256>>>(lower_src, upper_src, out);
}

// round 4
// speedup vs baseline: 2.0436x; 1.1615x over previous
#include <cuda_runtime.h>
#include <cuda_fp16.h>
#include <cstdint>

#define N_NODES 50000
#define N_EDGES 800000
#define IN_CH   256
#define HC      128
#define N_TOT   384          // [xm_lower | xm_upper | skip]
#define EPSF    (1.0f + 1e-6f)
#define NEG_SLOPE 0.01f

// ---------------- scratch (__device__ globals: no allocs allowed) ------------
__device__ __half g_Bh[(size_t)N_TOT * IN_CH];          // 192 KB, [n][k] half
__device__ float  g_XM[(size_t)N_NODES * N_TOT];        // 76.8 MB
__device__ float  g_asrc_l[N_NODES * 2];
__device__ float  g_adst_l[N_NODES * 2];
__device__ float  g_asrc_u[N_NODES * 2];
__device__ float  g_adst_u[N_NODES * 2];
__device__ int    g_off_l[N_NODES + 1];
__device__ int    g_off_u[N_NODES + 1];

// ---------------- pack: W_lower|W_upper|W_skip*EPS -> g_Bh half [n][k] -------
__global__ void pack_w_kernel(const float* __restrict__ Wl,
                              const float* __restrict__ Wu,
                              const float* __restrict__ Ws) {
    int i = blockIdx.x * blockDim.x + threadIdx.x;
    if (i >= N_TOT * IN_CH) return;
    int n = i / IN_CH, k = i % IN_CH;
    float v;
    if (n < 128)      v = Wl[k * HC + n];
    else if (n < 256) v = Wu[k * HC + (n - 128)];
    else              v = Ws[k * HC + (n - 256)] * EPSF;
    g_Bh[i] = __float2half_rn(v);
}

// ---------------- fp16 mma.sync GEMM: XM[50000,384] = x @ Wcat ---------------
#define BM 128
#define BN 128
#define BK 32
#define AH_STR 40    // halves per row (80B): 16B-aligned, conflict-free frags

__device__ __forceinline__ void cp_async16(uint32_t dst, const void* src) {
    asm volatile("cp.async.cg.shared.global [%0], [%1], 16;"
                 :: "r"(dst), "l"(src) : "memory");
}
#define CP_COMMIT() asm volatile("cp.async.commit_group;" ::: "memory")
#define CP_WAIT0()  asm volatile("cp.async.wait_group 0;" ::: "memory")

__device__ __forceinline__ void mma_f16(float* c, const uint32_t* a,
                                        uint32_t b0, uint32_t b1) {
    asm volatile(
        "mma.sync.aligned.m16n8k16.row.col.f32.f16.f16.f32 "
        "{%0,%1,%2,%3}, {%4,%5,%6,%7}, {%8,%9}, {%0,%1,%2,%3};"
        : "+f"(c[0]), "+f"(c[1]), "+f"(c[2]), "+f"(c[3])
        : "r"(a[0]), "r"(a[1]), "r"(a[2]), "r"(a[3]), "r"(b0), "r"(b1));
}

__global__ __launch_bounds__(256, 2) void gemm_kernel(const float* __restrict__ X) {
    __shared__ __half As[2][BM * AH_STR];   // 2 x 10 KB
    __shared__ __half Bs[2][BN * AH_STR];   // 2 x 10 KB

    const int t    = threadIdx.x;
    const int lane = t & 31;
    const int wid  = t >> 5;
    const int row0 = blockIdx.x * BM;
    const int col0 = blockIdx.y * BN;
    const int wm   = (wid & 3) * 32;
    const int wn   = (wid >> 2) * 64;
    const int g    = lane >> 2;
    const int c    = lane & 3;

    // per-thread A staging coords
    const int am = t >> 3;            // row 0..31 step: actually 0..127 over slots
    float4 av[4];

    float acc[2][8][4];
    #pragma unroll
    for (int mf = 0; mf < 2; mf++)
        #pragma unroll
        for (int nf = 0; nf < 8; nf++)
            #pragma unroll
            for (int j = 0; j < 4; j++) acc[mf][nf][j] = 0.f;

    auto load_a_regs = [&](int k0) {
        #pragma unroll
        for (int i = 0; i < 4; i++) {
            int slot = t + i * 256;
            int m    = slot >> 3;
            int k4   = (slot & 7) * 4;
            int gr   = row0 + m;
            av[i] = (gr < N_NODES)
                  ? *(const float4*)(X + (size_t)gr * IN_CH + k0 + k4)
                  : make_float4(0.f, 0.f, 0.f, 0.f);
        }
    };
    auto sts_a = [&](int buf) {
        #pragma unroll
        for (int i = 0; i < 4; i++) {
            int slot = t + i * 256;
            int m    = slot >> 3;
            int k4   = (slot & 7) * 4;
            __half2 h01 = __floats2half2_rn(av[i].x, av[i].y);
            __half2 h23 = __floats2half2_rn(av[i].z, av[i].w);
            __half2* p = (__half2*)&As[buf][m * AH_STR + k4];
            p[0] = h01; p[1] = h23;
        }
    };
    auto issue_b = [&](int k0, int buf) {
        uint32_t base = (uint32_t)__cvta_generic_to_shared(&Bs[buf][0]);
        #pragma unroll
        for (int i = 0; i < 2; i++) {
            int idx = t + i * 256;         // 0..511 16B chunks
            int n   = idx >> 2;
            int q   = idx & 3;
            cp_async16(base + (uint32_t)(n * AH_STR + q * 8) * 2,
                       g_Bh + (size_t)(col0 + n) * IN_CH + k0 + q * 8);
        }
    };

    // prologue
    load_a_regs(0);
    issue_b(0, 0);
    CP_COMMIT();
    sts_a(0);
    CP_WAIT0();
    __syncthreads();

    int buf = 0;
    for (int c8 = 0; c8 < 8; c8++) {
        int nxt = buf ^ 1;
        if (c8 < 7) {
            load_a_regs((c8 + 1) * BK);
            issue_b((c8 + 1) * BK, nxt);
            CP_COMMIT();
        }

        const __half* asb = &As[buf][0];
        const __half* bsb = &Bs[buf][0];
        #pragma unroll
        for (int ks = 0; ks < 2; ks++) {
            const int kb = ks * 16;
            uint32_t a[2][4];
            #pragma unroll
            for (int mf = 0; mf < 2; mf++) {
                int m = wm + mf * 16 + g;
                a[mf][0] = *(const uint32_t*)&asb[m * AH_STR + kb + c * 2];
                a[mf][1] = *(const uint32_t*)&asb[(m + 8) * AH_STR + kb + c * 2];
                a[mf][2] = *(const uint32_t*)&asb[m * AH_STR + kb + c * 2 + 8];
                a[mf][3] = *(const uint32_t*)&asb[(m + 8) * AH_STR + kb + c * 2 + 8];
            }
            #pragma unroll
            for (int nf = 0; nf < 8; nf++) {
                const __half* bp = &bsb[(wn + nf * 8 + g) * AH_STR + kb];
                uint32_t b0 = *(const uint32_t*)&bp[c * 2];
                uint32_t b1 = *(const uint32_t*)&bp[c * 2 + 8];
                mma_f16(acc[0][nf], a[0], b0, b1);
                mma_f16(acc[1][nf], a[1], b0, b1);
            }
        }

        if (c8 < 7) {
            sts_a(nxt);
            CP_WAIT0();
        }
        __syncthreads();
        buf = nxt;
    }
    (void)am;

    // epilogue: float2 stores straight to g_XM
    #pragma unroll
    for (int mf = 0; mf < 2; mf++) {
        int r1 = row0 + wm + mf * 16 + g;
        int r2 = r1 + 8;
        #pragma unroll
        for (int nf = 0; nf < 8; nf++) {
            int cc = col0 + wn + nf * 8 + c * 2;
            if (r1 < N_NODES)
                *(float2*)(g_XM + (size_t)r1 * N_TOT + cc) =
                    make_float2(acc[mf][nf][0], acc[mf][nf][1]);
            if (r2 < N_NODES)
                *(float2*)(g_XM + (size_t)r2 * N_TOT + cc) =
                    make_float2(acc[mf][nf][2], acc[mf][nf][3]);
        }
    }
}

// ---------------- merged: CSR offsets (shuffle) + per-node alphas ------------
#define OFF_BLOCKS ((N_EDGES + 1 + 255) / 256)          // 3126
#define ALPHA_BLOCKS ((N_NODES + 7) / 8)                // 6250

__device__ __forceinline__ float lrelu(float v) {
    return v >= 0.f ? v : NEG_SLOPE * v;
}

__global__ __launch_bounds__(256) void mid_kernel(
    const int* __restrict__ tl, const int* __restrict__ tu,
    const float* __restrict__ asl, const float* __restrict__ adl,
    const float* __restrict__ asu, const float* __restrict__ adu) {
    if (blockIdx.x < OFF_BLOCKS) {
        int e    = blockIdx.x * 256 + threadIdx.x;
        int lane = threadIdx.x & 31;
        int ec   = min(e, N_EDGES);
        int cl = (ec < N_EDGES) ? __ldg(tl + ec) : N_NODES;
        int cu = (ec < N_EDGES) ? __ldg(tu + ec) : N_NODES;
        int pl = __shfl_up_sync(0xFFFFFFFFu, cl, 1);
        int pu = __shfl_up_sync(0xFFFFFFFFu, cu, 1);
        if (lane == 0) {
            pl = (ec > 0) ? __ldg(tl + ec - 1) : -1;
            pu = (ec > 0) ? __ldg(tu + ec - 1) : -1;
        }
        if (e <= N_EDGES) {
            for (int v = pl + 1; v <= cl; v++) g_off_l[v] = e;
            for (int v = pu + 1; v <= cu; v++) g_off_u[v] = e;
        }
        return;
    }
    // ---- alpha part: warp per node ----
    int node = (blockIdx.x - OFF_BLOCKS) * 8 + (threadIdx.x >> 5);
    int lane = threadIdx.x & 31;
    if (node >= N_NODES) return;

    const float* row = g_XM + (size_t)node * N_TOT;
    float4 xl  = *(const float4*)(row + lane * 4);
    float4 xu  = *(const float4*)(row + 128 + lane * 4);
    float4 vsl = *(const float4*)(asl + lane * 4);
    float4 vdl = *(const float4*)(adl + lane * 4);
    float4 vsu = *(const float4*)(asu + lane * 4);
    float4 vdu = *(const float4*)(adu + lane * 4);

    float psl = xl.x * vsl.x + xl.y * vsl.y + xl.z * vsl.z + xl.w * vsl.w;
    float pdl = xl.x * vdl.x + xl.y * vdl.y + xl.z * vdl.z + xl.w * vdl.w;
    float psu = xu.x * vsu.x + xu.y * vsu.y + xu.z * vsu.z + xu.w * vsu.w;
    float pdu = xu.x * vdu.x + xu.y * vdu.y + xu.z * vdu.z + xu.w * vdu.w;

    #pragma unroll
    for (int m = 8; m >= 1; m >>= 1) {
        psl += __shfl_xor_sync(0xFFFFFFFFu, psl, m);
        pdl += __shfl_xor_sync(0xFFFFFFFFu, pdl, m);
        psu += __shfl_xor_sync(0xFFFFFFFFu, psu, m);
        pdu += __shfl_xor_sync(0xFFFFFFFFu, pdu, m);
    }
    if (lane == 0 || lane == 16) {
        int h = lane >> 4;
        g_asrc_l[node * 2 + h] = lrelu(psl);
        g_adst_l[node * 2 + h] = lrelu(pdl);
        g_asrc_u[node * 2 + h] = lrelu(psu);
        g_adst_u[node * 2 + h] = lrelu(pdu);
    }
}

// ---------------- fused aggregation: skip + lower + upper + relu -------------
// Warp per node; lanes 0-15 head 0, 16-31 head 1; 4 channels/lane.
// Per-edge `vals` cancel in the head-axis softmax -> never loaded.
__global__ __launch_bounds__(256) void aggregate_kernel(
    const int* __restrict__ srcL, const int* __restrict__ srcU,
    float* __restrict__ out) {
    int wid  = (blockIdx.x * blockDim.x + threadIdx.x) >> 5;
    int lane = threadIdx.x & 31;
    if (wid >= N_NODES) return;

    const bool h0 = lane < 16;
    float4 acc = *(const float4*)(g_XM + (size_t)wid * N_TOT + 256 + lane * 4);

    {
        float2 ad = *(const float2*)(g_adst_l + wid * 2);
        int e1 = g_off_l[wid + 1];
        #pragma unroll 2
        for (int e = g_off_l[wid]; e < e1; e++) {
            int s = __ldg(srcL + e);
            float2 as = *(const float2*)(g_asrc_l + 2 * s);
            float s0 = as.x + ad.x, s1 = as.y + ad.y;
            float d  = h0 ? (s1 - s0) : (s0 - s1);
            float w  = 1.f / (1.f + __expf(d));
            float4 xv = *(const float4*)(g_XM + (size_t)s * N_TOT + lane * 4);
            acc.x += xv.x * w; acc.y += xv.y * w;
            acc.z += xv.z * w; acc.w += xv.w * w;
        }
    }
    {
        float2 ad = *(const float2*)(g_adst_u + wid * 2);
        int e1 = g_off_u[wid + 1];
        #pragma unroll 2
        for (int e = g_off_u[wid]; e < e1; e++) {
            int s = __ldg(srcU + e);
            float2 as = *(const float2*)(g_asrc_u + 2 * s);
            float s0 = as.x + ad.x, s1 = as.y + ad.y;
            float d  = h0 ? (s1 - s0) : (s0 - s1);
            float w  = 1.f / (1.f + __expf(d));
            float4 xv = *(const float4*)(g_XM + (size_t)s * N_TOT + 128 + lane * 4);
            acc.x += xv.x * w; acc.y += xv.y * w;
            acc.z += xv.z * w; acc.w += xv.w * w;
        }
    }

    acc.x = fmaxf(acc.x, 0.f); acc.y = fmaxf(acc.y, 0.f);
    acc.z = fmaxf(acc.z, 0.f); acc.w = fmaxf(acc.w, 0.f);
    *(float4*)(out + (size_t)wid * HC + lane * 4) = acc;
}

// ---------------- launch ------------------------------------------------------
extern "C" void kernel_launch(void* const* d_in, const int* in_sizes, int n_in,
                              void* d_out, int out_size) {
    const float* x         = (const float*)d_in[0];
    const int*   lower_tgt = (const int*)  d_in[1];
    const int*   lower_src = (const int*)  d_in[2];
    const int*   upper_tgt = (const int*)  d_in[4];
    const int*   upper_src = (const int*)  d_in[5];
    const float* W_lower   = (const float*)d_in[7];
    const float* a_src_l   = (const float*)d_in[8];
    const float* a_dst_l   = (const float*)d_in[9];
    const float* W_upper   = (const float*)d_in[10];
    const float* a_src_u   = (const float*)d_in[11];
    const float* a_dst_u   = (const float*)d_in[12];
    const float* W_skip    = (const float*)d_in[13];
    float* out = (float*)d_out;

    pack_w_kernel<<<(N_TOT * IN_CH + 255) / 256, 256>>>(W_lower, W_upper, W_skip);

    dim3 gg((N_NODES + BM - 1) / BM, N_TOT / BN);   // 391 x 3
    gemm_kernel<<<gg, 256>>>(x);

    mid_kernel<<<OFF_BLOCKS + ALPHA_BLOCKS, 256>>>(lower_tgt, upper_tgt,
                                                   a_src_l, a_dst_l,
                                                   a_src_u, a_dst_u);
    aggregate_kernel<<<(N_NODES * 32 + 255) / 256, 256>>>(lower_src, upper_src, out);
}

// round 5
// speedup vs baseline: 2.7613x; 1.3512x over previous
#include <cuda_runtime.h>
#include <cuda_fp16.h>
#include <cstdint>

#define N_NODES 50000
#define N_EDGES 800000
#define IN_CH   256
#define HC      128
#define N_TOT   384          // [xm_lower | xm_upper | skip]
#define EPSF    (1.0f + 1e-6f)
#define NEG_SLOPE 0.01f

// ---------------- scratch (__device__ globals: no allocs allowed) ------------
__device__ __half g_Bh[(size_t)N_TOT * IN_CH];          // 192 KB, [n][k] half
__device__ __half g_XMh[(size_t)N_NODES * 256];         // 25.6 MB [lower|upper]
__device__ float  g_Xskip[(size_t)N_NODES * HC];        // 25.6 MB
__device__ float  g_asrc_l[N_NODES * 2];
__device__ float  g_adst_l[N_NODES * 2];
__device__ float  g_asrc_u[N_NODES * 2];
__device__ float  g_adst_u[N_NODES * 2];
__device__ float  g_wL[N_EDGES];                        // head-0 weight per edge
__device__ float  g_wU[N_EDGES];
__device__ int    g_off_l[N_NODES + 1];
__device__ int    g_off_u[N_NODES + 1];

// ---------------- pack: W_lower|W_upper|W_skip*EPS -> g_Bh half [n][k] -------
__global__ void pack_w_kernel(const float* __restrict__ Wl,
                              const float* __restrict__ Wu,
                              const float* __restrict__ Ws) {
    int i = blockIdx.x * blockDim.x + threadIdx.x;
    if (i >= N_TOT * IN_CH) return;
    int n = i / IN_CH, k = i % IN_CH;
    float v;
    if (n < 128)      v = Wl[k * HC + n];
    else if (n < 256) v = Wu[k * HC + (n - 128)];
    else              v = Ws[k * HC + (n - 256)] * EPSF;
    g_Bh[i] = __float2half_rn(v);
}

// ---------------- fp16 mma.sync GEMM ----------------------------------------
#define BM 128
#define BN 128
#define BK 32
#define AH_STR 40

__device__ __forceinline__ void cp_async16(uint32_t dst, const void* src) {
    asm volatile("cp.async.cg.shared.global [%0], [%1], 16;"
                 :: "r"(dst), "l"(src) : "memory");
}
#define CP_COMMIT() asm volatile("cp.async.commit_group;" ::: "memory")
#define CP_WAIT0()  asm volatile("cp.async.wait_group 0;" ::: "memory")

__device__ __forceinline__ void mma_f16(float* c, const uint32_t* a,
                                        uint32_t b0, uint32_t b1) {
    asm volatile(
        "mma.sync.aligned.m16n8k16.row.col.f32.f16.f16.f32 "
        "{%0,%1,%2,%3}, {%4,%5,%6,%7}, {%8,%9}, {%0,%1,%2,%3};"
        : "+f"(c[0]), "+f"(c[1]), "+f"(c[2]), "+f"(c[3])
        : "r"(a[0]), "r"(a[1]), "r"(a[2]), "r"(a[3]), "r"(b0), "r"(b1));
}

__global__ __launch_bounds__(256, 2) void gemm_kernel(const float* __restrict__ X) {
    __shared__ __half As[2][BM * AH_STR];
    __shared__ __half Bs[2][BN * AH_STR];

    const int t    = threadIdx.x;
    const int lane = t & 31;
    const int wid  = t >> 5;
    const int row0 = blockIdx.x * BM;
    const int col0 = blockIdx.y * BN;
    const int wm   = (wid & 3) * 32;
    const int wn   = (wid >> 2) * 64;
    const int g    = lane >> 2;
    const int c    = lane & 3;

    float4 av[4];
    float acc[2][8][4];
    #pragma unroll
    for (int mf = 0; mf < 2; mf++)
        #pragma unroll
        for (int nf = 0; nf < 8; nf++)
            #pragma unroll
            for (int j = 0; j < 4; j++) acc[mf][nf][j] = 0.f;

    auto load_a_regs = [&](int k0) {
        #pragma unroll
        for (int i = 0; i < 4; i++) {
            int slot = t + i * 256;
            int m    = slot >> 3;
            int k4   = (slot & 7) * 4;
            int gr   = row0 + m;
            av[i] = (gr < N_NODES)
                  ? *(const float4*)(X + (size_t)gr * IN_CH + k0 + k4)
                  : make_float4(0.f, 0.f, 0.f, 0.f);
        }
    };
    auto sts_a = [&](int buf) {
        #pragma unroll
        for (int i = 0; i < 4; i++) {
            int slot = t + i * 256;
            int m    = slot >> 3;
            int k4   = (slot & 7) * 4;
            __half2* p = (__half2*)&As[buf][m * AH_STR + k4];
            p[0] = __floats2half2_rn(av[i].x, av[i].y);
            p[1] = __floats2half2_rn(av[i].z, av[i].w);
        }
    };
    auto issue_b = [&](int k0, int buf) {
        uint32_t base = (uint32_t)__cvta_generic_to_shared(&Bs[buf][0]);
        #pragma unroll
        for (int i = 0; i < 2; i++) {
            int idx = t + i * 256;
            int n   = idx >> 2;
            int q   = idx & 3;
            cp_async16(base + (uint32_t)(n * AH_STR + q * 8) * 2,
                       g_Bh + (size_t)(col0 + n) * IN_CH + k0 + q * 8);
        }
    };

    load_a_regs(0);
    issue_b(0, 0);
    CP_COMMIT();
    sts_a(0);
    CP_WAIT0();
    __syncthreads();

    int buf = 0;
    for (int c8 = 0; c8 < 8; c8++) {
        int nxt = buf ^ 1;
        if (c8 < 7) {
            load_a_regs((c8 + 1) * BK);
            issue_b((c8 + 1) * BK, nxt);
            CP_COMMIT();
        }
        const __half* asb = &As[buf][0];
        const __half* bsb = &Bs[buf][0];
        #pragma unroll
        for (int ks = 0; ks < 2; ks++) {
            const int kb = ks * 16;
            uint32_t a[2][4];
            #pragma unroll
            for (int mf = 0; mf < 2; mf++) {
                int m = wm + mf * 16 + g;
                a[mf][0] = *(const uint32_t*)&asb[m * AH_STR + kb + c * 2];
                a[mf][1] = *(const uint32_t*)&asb[(m + 8) * AH_STR + kb + c * 2];
                a[mf][2] = *(const uint32_t*)&asb[m * AH_STR + kb + c * 2 + 8];
                a[mf][3] = *(const uint32_t*)&asb[(m + 8) * AH_STR + kb + c * 2 + 8];
            }
            #pragma unroll
            for (int nf = 0; nf < 8; nf++) {
                const __half* bp = &bsb[(wn + nf * 8 + g) * AH_STR + kb];
                uint32_t b0 = *(const uint32_t*)&bp[c * 2];
                uint32_t b1 = *(const uint32_t*)&bp[c * 2 + 8];
                mma_f16(acc[0][nf], a[0], b0, b1);
                mma_f16(acc[1][nf], a[1], b0, b1);
            }
        }
        if (c8 < 7) {
            sts_a(nxt);
            CP_WAIT0();
        }
        __syncthreads();
        buf = nxt;
    }

    // epilogue: lower/upper -> half g_XMh, skip -> fp32 g_Xskip
    #pragma unroll
    for (int mf = 0; mf < 2; mf++) {
        int r1 = row0 + wm + mf * 16 + g;
        int r2 = r1 + 8;
        #pragma unroll
        for (int nf = 0; nf < 8; nf++) {
            int cc = wn + nf * 8 + c * 2;
            if (blockIdx.y < 2) {
                int coff = blockIdx.y * 128 + cc;
                if (r1 < N_NODES)
                    *(__half2*)(g_XMh + (size_t)r1 * 256 + coff) =
                        __floats2half2_rn(acc[mf][nf][0], acc[mf][nf][1]);
                if (r2 < N_NODES)
                    *(__half2*)(g_XMh + (size_t)r2 * 256 + coff) =
                        __floats2half2_rn(acc[mf][nf][2], acc[mf][nf][3]);
            } else {
                if (r1 < N_NODES)
                    *(float2*)(g_Xskip + (size_t)r1 * HC + cc) =
                        make_float2(acc[mf][nf][0], acc[mf][nf][1]);
                if (r2 < N_NODES)
                    *(float2*)(g_Xskip + (size_t)r2 * HC + cc) =
                        make_float2(acc[mf][nf][2], acc[mf][nf][3]);
            }
        }
    }
}

// ---------------- merged: CSR offsets (shuffle) + per-node alphas ------------
#define OFF_BLOCKS ((N_EDGES + 1 + 255) / 256)          // 3126
#define ALPHA_BLOCKS ((N_NODES + 7) / 8)                // 6250

__device__ __forceinline__ float lrelu(float v) {
    return v >= 0.f ? v : NEG_SLOPE * v;
}

__global__ __launch_bounds__(256) void mid_kernel(
    const int* __restrict__ tl, const int* __restrict__ tu,
    const float* __restrict__ asl, const float* __restrict__ adl,
    const float* __restrict__ asu, const float* __restrict__ adu) {
    if (blockIdx.x < OFF_BLOCKS) {
        int e    = blockIdx.x * 256 + threadIdx.x;
        int lane = threadIdx.x & 31;
        int ec   = min(e, N_EDGES);
        int cl = (ec < N_EDGES) ? __ldg(tl + ec) : N_NODES;
        int cu = (ec < N_EDGES) ? __ldg(tu + ec) : N_NODES;
        int pl = __shfl_up_sync(0xFFFFFFFFu, cl, 1);
        int pu = __shfl_up_sync(0xFFFFFFFFu, cu, 1);
        if (lane == 0) {
            pl = (ec > 0) ? __ldg(tl + ec - 1) : -1;
            pu = (ec > 0) ? __ldg(tu + ec - 1) : -1;
        }
        if (e <= N_EDGES) {
            for (int v = pl + 1; v <= cl; v++) g_off_l[v] = e;
            for (int v = pu + 1; v <= cu; v++) g_off_u[v] = e;
        }
        return;
    }
    // ---- alpha part: warp per node, xm rows now half ----
    int node = (blockIdx.x - OFF_BLOCKS) * 8 + (threadIdx.x >> 5);
    int lane = threadIdx.x & 31;
    if (node >= N_NODES) return;

    const __half* row = g_XMh + (size_t)node * 256;
    uint2 ul = *(const uint2*)(row + lane * 4);
    uint2 uu = *(const uint2*)(row + 128 + lane * 4);
    float2 xl0 = __half22float2(*(__half2*)&ul.x);
    float2 xl1 = __half22float2(*(__half2*)&ul.y);
    float2 xu0 = __half22float2(*(__half2*)&uu.x);
    float2 xu1 = __half22float2(*(__half2*)&uu.y);
    float4 vsl = *(const float4*)(asl + lane * 4);
    float4 vdl = *(const float4*)(adl + lane * 4);
    float4 vsu = *(const float4*)(asu + lane * 4);
    float4 vdu = *(const float4*)(adu + lane * 4);

    float psl = xl0.x * vsl.x + xl0.y * vsl.y + xl1.x * vsl.z + xl1.y * vsl.w;
    float pdl = xl0.x * vdl.x + xl0.y * vdl.y + xl1.x * vdl.z + xl1.y * vdl.w;
    float psu = xu0.x * vsu.x + xu0.y * vsu.y + xu1.x * vsu.z + xu1.y * vsu.w;
    float pdu = xu0.x * vdu.x + xu0.y * vdu.y + xu1.x * vdu.z + xu1.y * vdu.w;

    #pragma unroll
    for (int m = 8; m >= 1; m >>= 1) {
        psl += __shfl_xor_sync(0xFFFFFFFFu, psl, m);
        pdl += __shfl_xor_sync(0xFFFFFFFFu, pdl, m);
        psu += __shfl_xor_sync(0xFFFFFFFFu, psu, m);
        pdu += __shfl_xor_sync(0xFFFFFFFFu, pdu, m);
    }
    if (lane == 0 || lane == 16) {
        int h = lane >> 4;
        g_asrc_l[node * 2 + h] = lrelu(psl);
        g_adst_l[node * 2 + h] = lrelu(pdl);
        g_asrc_u[node * 2 + h] = lrelu(psu);
        g_adst_u[node * 2 + h] = lrelu(pdu);
    }
}

// ---------------- per-edge softmax weights (head 0; head 1 = 1-w) ------------
__global__ __launch_bounds__(256) void weight_kernel(
    const int* __restrict__ tl, const int* __restrict__ sl,
    const int* __restrict__ tu, const int* __restrict__ su) {
    int e = blockIdx.x * blockDim.x + threadIdx.x;
    if (e >= N_EDGES) return;
    {
        int tt = __ldg(tl + e), ss = __ldg(sl + e);
        float2 as = *(const float2*)(g_asrc_l + 2 * ss);
        float2 ad = *(const float2*)(g_adst_l + 2 * tt);
        float d = (as.y + ad.y) - (as.x + ad.x);   // s1 - s0
        g_wL[e] = __fdividef(1.f, 1.f + __expf(d));
    }
    {
        int tt = __ldg(tu + e), ss = __ldg(su + e);
        float2 as = *(const float2*)(g_asrc_u + 2 * ss);
        float2 ad = *(const float2*)(g_adst_u + 2 * tt);
        float d = (as.y + ad.y) - (as.x + ad.x);
        g_wU[e] = __fdividef(1.f, 1.f + __expf(d));
    }
}

// ---------------- fused aggregation: skip + lower + upper + relu -------------
// Warp per node; lanes 0-15 head 0, 16-31 head 1; 4 channels/lane.
__global__ __launch_bounds__(256) void aggregate_kernel(
    const int* __restrict__ srcL, const int* __restrict__ srcU,
    float* __restrict__ out) {
    int wid  = (blockIdx.x * blockDim.x + threadIdx.x) >> 5;
    int lane = threadIdx.x & 31;
    if (wid >= N_NODES) return;

    const bool h0 = lane < 16;
    float4 acc = *(const float4*)(g_Xskip + (size_t)wid * HC + lane * 4);

    #pragma unroll
    for (int part = 0; part < 2; part++) {
        const int*   src = part ? srcU : srcL;
        const float* wgt = part ? g_wU : g_wL;
        const int*   off = part ? g_off_u : g_off_l;
        const int    coff = part * 128 + lane * 4;
        int e  = off[wid];
        int e1 = off[wid + 1];
        for (; e + 1 < e1; e += 2) {
            int   sa = __ldg(src + e),     sb = __ldg(src + e + 1);
            float wa = __ldg(wgt + e),     wb = __ldg(wgt + e + 1);
            uint2 ua = *(const uint2*)(g_XMh + (size_t)sa * 256 + coff);
            uint2 ub = *(const uint2*)(g_XMh + (size_t)sb * 256 + coff);
            wa = h0 ? wa : 1.f - wa;
            wb = h0 ? wb : 1.f - wb;
            float2 a0 = __half22float2(*(__half2*)&ua.x);
            float2 a1 = __half22float2(*(__half2*)&ua.y);
            float2 b0 = __half22float2(*(__half2*)&ub.x);
            float2 b1 = __half22float2(*(__half2*)&ub.y);
            acc.x += a0.x * wa + b0.x * wb;
            acc.y += a0.y * wa + b0.y * wb;
            acc.z += a1.x * wa + b1.x * wb;
            acc.w += a1.y * wa + b1.y * wb;
        }
        if (e < e1) {
            int   sa = __ldg(src + e);
            float wa = __ldg(wgt + e);
            uint2 ua = *(const uint2*)(g_XMh + (size_t)sa * 256 + coff);
            wa = h0 ? wa : 1.f - wa;
            float2 a0 = __half22float2(*(__half2*)&ua.x);
            float2 a1 = __half22float2(*(__half2*)&ua.y);
            acc.x += a0.x * wa; acc.y += a0.y * wa;
            acc.z += a1.x * wa; acc.w += a1.y * wa;
        }
    }

    acc.x = fmaxf(acc.x, 0.f); acc.y = fmaxf(acc.y, 0.f);
    acc.z = fmaxf(acc.z, 0.f); acc.w = fmaxf(acc.w, 0.f);
    *(float4*)(out + (size_t)wid * HC + lane * 4) = acc;
}

// ---------------- launch ------------------------------------------------------
extern "C" void kernel_launch(void* const* d_in, const int* in_sizes, int n_in,
                              void* d_out, int out_size) {
    const float* x         = (const float*)d_in[0];
    const int*   lower_tgt = (const int*)  d_in[1];
    const int*   lower_src = (const int*)  d_in[2];
    const int*   upper_tgt = (const int*)  d_in[4];
    const int*   upper_src = (const int*)  d_in[5];
    const float* W_lower   = (const float*)d_in[7];
    const float* a_src_l   = (const float*)d_in[8];
    const float* a_dst_l   = (const float*)d_in[9];
    const float* W_upper   = (const float*)d_in[10];
    const float* a_src_u   = (const float*)d_in[11];
    const float* a_dst_u   = (const float*)d_in[12];
    const float* W_skip    = (const float*)d_in[13];
    float* out = (float*)d_out;

    pack_w_kernel<<<(N_TOT * IN_CH + 255) / 256, 256>>>(W_lower, W_upper, W_skip);

    dim3 gg((N_NODES + BM - 1) / BM, N_TOT / BN);   // 391 x 3
    gemm_kernel<<<gg, 256>>>(x);

    mid_kernel<<<OFF_BLOCKS + ALPHA_BLOCKS, 256>>>(lower_tgt, upper_tgt,
                                                   a_src_l, a_dst_l,
                                                   a_src_u, a_dst_u);
    weight_kernel<<<(N_EDGES + 255) / 256, 256>>>(lower_tgt, lower_src,
                                                  upper_tgt, upper_src);
    aggregate_kernel<<<(N_NODES * 32 + 255) / 256, 256>>>(lower_src, upper_src, out);
}